// round 1
// baseline (speedup 1.0000x reference)
#include <cuda_runtime.h>
#include <math.h>

#define N 8192
#define D 512
#define TI 64
#define TJ 64
#define KC 16

// 1/POS_W = 1/NEG_W = 2.0
__device__ __constant__ float INV_POS_W = 2.0f;
__device__ __constant__ float INV_NEG_W = 2.0f;

// Scratch (device globals: no allocation allowed)
__device__ float g_ne[(size_t)N * D];   // normalized embeddings, 16 MB
__device__ float g_pos[N];              // cos(e_i, t_i)
__device__ float g_lp[N];               // per-row loss partial

// ---------------------------------------------------------------------------
// K1: per-row normalization of embeddings + pos_i = cos(e_i, t_i)
// One block per row, 128 threads, each handles 4 contiguous floats (float4).
// ---------------------------------------------------------------------------
__global__ __launch_bounds__(128) void prep_kernel(const float* __restrict__ E,
                                                   const float* __restrict__ T) {
    const int i   = blockIdx.x;
    const int tid = threadIdx.x;

    float4 ev = reinterpret_cast<const float4*>(E + (size_t)i * D)[tid];
    float4 tv = reinterpret_cast<const float4*>(T + (size_t)i * D)[tid];

    float se  = ev.x * ev.x + ev.y * ev.y + ev.z * ev.z + ev.w * ev.w;
    float st  = tv.x * tv.x + tv.y * tv.y + tv.z * tv.z + tv.w * tv.w;
    float set = ev.x * tv.x + ev.y * tv.y + ev.z * tv.z + ev.w * tv.w;

    #pragma unroll
    for (int o = 16; o > 0; o >>= 1) {
        se  += __shfl_xor_sync(0xffffffffu, se,  o);
        st  += __shfl_xor_sync(0xffffffffu, st,  o);
        set += __shfl_xor_sync(0xffffffffu, set, o);
    }

    __shared__ float sh[3][4];
    const int w = tid >> 5, l = tid & 31;
    if (l == 0) { sh[0][w] = se; sh[1][w] = st; sh[2][w] = set; }
    __syncthreads();

    se  = sh[0][0] + sh[0][1] + sh[0][2] + sh[0][3];
    st  = sh[1][0] + sh[1][1] + sh[1][2] + sh[1][3];
    set = sh[2][0] + sh[2][1] + sh[2][2] + sh[2][3];

    const float inv_e = 1.0f / fmaxf(sqrtf(se), 1e-12f);

    float4 o;
    o.x = ev.x * inv_e; o.y = ev.y * inv_e; o.z = ev.z * inv_e; o.w = ev.w * inv_e;
    reinterpret_cast<float4*>(g_ne + (size_t)i * D)[tid] = o;

    if (tid == 0) {
        const float inv_t = 1.0f / fmaxf(sqrtf(st), 1e-12f);
        g_pos[i] = set * inv_e * inv_t;
    }
}

// ---------------------------------------------------------------------------
// K2: fused sim-GEMM + exp + row-sum.
// Block = 256 threads (16x16), handles TI=64 i-rows for ALL j (no atomics).
// 4x4 register micro-tile per thread; smem tiles stored k-major for
// conflict-light float4 compute loads.
// ---------------------------------------------------------------------------
__global__ __launch_bounds__(256) void sim_kernel() {
    __shared__ float As[KC][TI + 4];
    __shared__ float Bs[KC][TJ + 4];
    __shared__ float Red[TI][17];

    const int iBase = blockIdx.x * TI;
    const int tid   = threadIdx.x;
    const int tx    = tid & 15;        // j micro-tile index
    const int ty    = tid >> 4;        // i micro-tile index

    // load mapping: each thread loads one float4 along k
    const int lrow = tid >> 2;         // 0..63 (tile-local row)
    const int lk4  = (tid & 3) * 4;    // 0,4,8,12

    float rs[4] = {0.f, 0.f, 0.f, 0.f};

    for (int jBase = 0; jBase < N; jBase += TJ) {
        float acc[4][4];
        #pragma unroll
        for (int r = 0; r < 4; r++)
            #pragma unroll
            for (int c = 0; c < 4; c++) acc[r][c] = 0.f;

        for (int k0 = 0; k0 < D; k0 += KC) {
            const float4 av = *reinterpret_cast<const float4*>(
                &g_ne[(size_t)(iBase + lrow) * D + k0 + lk4]);
            const float4 bv = *reinterpret_cast<const float4*>(
                &g_ne[(size_t)(jBase + lrow) * D + k0 + lk4]);

            __syncthreads();   // previous chunk fully consumed before overwrite
            As[lk4 + 0][lrow] = av.x;
            As[lk4 + 1][lrow] = av.y;
            As[lk4 + 2][lrow] = av.z;
            As[lk4 + 3][lrow] = av.w;
            Bs[lk4 + 0][lrow] = bv.x;
            Bs[lk4 + 1][lrow] = bv.y;
            Bs[lk4 + 2][lrow] = bv.z;
            Bs[lk4 + 3][lrow] = bv.w;
            __syncthreads();

            #pragma unroll
            for (int kk = 0; kk < KC; kk++) {
                const float4 a = *reinterpret_cast<const float4*>(&As[kk][ty * 4]);
                const float4 b = *reinterpret_cast<const float4*>(&Bs[kk][tx * 4]);
                acc[0][0] += a.x * b.x; acc[0][1] += a.x * b.y;
                acc[0][2] += a.x * b.z; acc[0][3] += a.x * b.w;
                acc[1][0] += a.y * b.x; acc[1][1] += a.y * b.y;
                acc[1][2] += a.y * b.z; acc[1][3] += a.y * b.w;
                acc[2][0] += a.z * b.x; acc[2][1] += a.z * b.y;
                acc[2][2] += a.z * b.z; acc[2][3] += a.z * b.w;
                acc[3][0] += a.w * b.x; acc[3][1] += a.w * b.y;
                acc[3][2] += a.w * b.z; acc[3][3] += a.w * b.w;
            }
        }

        // fold this j-tile into the running row sums: exp(2*sim)
        #pragma unroll
        for (int r = 0; r < 4; r++) {
            rs[r] += __expf(2.0f * acc[r][0]) + __expf(2.0f * acc[r][1]) +
                     __expf(2.0f * acc[r][2]) + __expf(2.0f * acc[r][3]);
        }
    }

    // cross-thread reduction: 16 tx-threads share each i row
    __syncthreads();
    #pragma unroll
    for (int r = 0; r < 4; r++) Red[ty * 4 + r][tx] = rs[r];
    __syncthreads();

    if (tid < TI) {
        float s = 0.f;
        #pragma unroll
        for (int c = 0; c < 16; c++) s += Red[tid][c];
        const int i = iBase + tid;
        // loss_partial_i = log(sum_j exp(2 neg_ij)) - 2 * pos_i
        g_lp[i] = logf(s) - INV_POS_W * g_pos[i];
    }
}

// ---------------------------------------------------------------------------
// K3: final scalar reduction
// ---------------------------------------------------------------------------
__global__ __launch_bounds__(256) void reduce_kernel(float* __restrict__ out) {
    const int tid = threadIdx.x;
    float s = 0.f;
    for (int i = tid; i < N; i += 256) s += g_lp[i];

    #pragma unroll
    for (int o = 16; o > 0; o >>= 1) s += __shfl_xor_sync(0xffffffffu, s, o);

    __shared__ float sh[8];
    const int w = tid >> 5, l = tid & 31;
    if (l == 0) sh[w] = s;
    __syncthreads();
    if (tid == 0) {
        float t = 0.f;
        #pragma unroll
        for (int i = 0; i < 8; i++) t += sh[i];
        out[0] = t / (2.0f * (float)N);
    }
}

// ---------------------------------------------------------------------------
extern "C" void kernel_launch(void* const* d_in, const int* in_sizes, int n_in,
                              void* d_out, int out_size) {
    const float* embeddings = (const float*)d_in[0];
    const float* targets    = (const float*)d_in[1];
    float* out = (float*)d_out;
    (void)in_sizes; (void)n_in; (void)out_size;

    prep_kernel<<<N, 128>>>(embeddings, targets);
    sim_kernel<<<N / TI, 256>>>();
    reduce_kernel<<<1, 256>>>(out);
}

// round 4
// speedup vs baseline: 15.7751x; 15.7751x over previous
#include <cuda_runtime.h>
#include <cuda_bf16.h>
#include <math.h>
#include <cstdint>

#define N 8192
#define D 512

// ---------------------------------------------------------------------------
// Device scratch (no allocations allowed)
// ---------------------------------------------------------------------------
__device__ __nv_bfloat16 g_neb[(size_t)N * D];  // normalized embeddings, bf16, 8 MB
__device__ float g_pos[N];                      // cos(e_i, t_i), fp32
__device__ float g_rs[2 * N];                   // per-(j-half) row sums of exp

__device__ __forceinline__ uint32_t smem_u32(const void* p) {
    uint32_t a;
    asm("{ .reg .u64 t; cvta.to.shared.u64 t, %1; cvt.u32.u64 %0, t; }" : "=r"(a) : "l"(p));
    return a;
}
__device__ __forceinline__ float ex2f(float x) {
    float y; asm("ex2.approx.ftz.f32 %0, %1;" : "=f"(y) : "f"(x)); return y;
}

#define CEXP 2.88539008177793f   /* 2*log2(e): exp(2x) = ex2(x*CEXP) */

// ---------------------------------------------------------------------------
// K1: per-row normalization (fp32 math) -> bf16 output + fp32 pos
// ---------------------------------------------------------------------------
__global__ __launch_bounds__(128) void prep_kernel(const float* __restrict__ E,
                                                   const float* __restrict__ T) {
    const int i   = blockIdx.x;
    const int tid = threadIdx.x;

    float4 ev = reinterpret_cast<const float4*>(E + (size_t)i * D)[tid];
    float4 tv = reinterpret_cast<const float4*>(T + (size_t)i * D)[tid];

    float se  = ev.x * ev.x + ev.y * ev.y + ev.z * ev.z + ev.w * ev.w;
    float st  = tv.x * tv.x + tv.y * tv.y + tv.z * tv.z + tv.w * tv.w;
    float set = ev.x * tv.x + ev.y * tv.y + ev.z * tv.z + ev.w * tv.w;

    #pragma unroll
    for (int o = 16; o > 0; o >>= 1) {
        se  += __shfl_xor_sync(0xffffffffu, se,  o);
        st  += __shfl_xor_sync(0xffffffffu, st,  o);
        set += __shfl_xor_sync(0xffffffffu, set, o);
    }

    __shared__ float sh[3][4];
    const int w = tid >> 5, l = tid & 31;
    if (l == 0) { sh[0][w] = se; sh[1][w] = st; sh[2][w] = set; }
    __syncthreads();

    se  = sh[0][0] + sh[0][1] + sh[0][2] + sh[0][3];
    st  = sh[1][0] + sh[1][1] + sh[1][2] + sh[1][3];
    set = sh[2][0] + sh[2][1] + sh[2][2] + sh[2][3];

    const float inv_e = 1.0f / fmaxf(sqrtf(se), 1e-12f);

    __nv_bfloat162 h0 = __floats2bfloat162_rn(ev.x * inv_e, ev.y * inv_e);
    __nv_bfloat162 h1 = __floats2bfloat162_rn(ev.z * inv_e, ev.w * inv_e);
    uint2 packed;
    packed.x = *reinterpret_cast<uint32_t*>(&h0);
    packed.y = *reinterpret_cast<uint32_t*>(&h1);
    reinterpret_cast<uint2*>(g_neb + (size_t)i * D)[tid] = packed;

    if (tid == 0) {
        const float inv_t = 1.0f / fmaxf(sqrtf(st), 1e-12f);
        g_pos[i] = set * inv_e * inv_t;
    }
}

// ---------------------------------------------------------------------------
// K2: fused mma.sync (HMMA bf16) sim-GEMM + exp + row-sum.
// Grid (64, 2): bx = i-tile (128 rows), by = j-half (4096 cols).
// 256 threads = 8 warps (m2 x n4), warp tile 64x64, CTA tile 128x256.
// SMEM: A resident 128x512 bf16 (8 chunks of 128x64, 128B rows, xor-swizzled),
//       B double buffer 2 x (256x64) bf16. 192 KB total.
// ---------------------------------------------------------------------------
#define A_CH 16384
#define B_CH 32768
#define SMEM_REQ (8 * A_CH + 2 * B_CH)

__global__ __launch_bounds__(256, 1)
void sim_kernel() {
    extern __shared__ __align__(1024) char smem[];
    const uint32_t sb  = smem_u32(smem);
    const uint32_t Ab  = sb;
    const uint32_t Bb0 = sb + 8 * A_CH;
    const uint32_t Bb1 = Bb0 + B_CH;

    const int tid = threadIdx.x;
    const int wid = tid >> 5;
    const int l   = tid & 31;
    const int mw  = wid & 1;       // warp row (0..1)  -> rows mw*64
    const int nw  = wid >> 1;      // warp col (0..3)  -> cols nw*64
    const int iBase = blockIdx.x * 128;
    const int jHalf = blockIdx.y * (N / 2);

    // ---- A tile load (cp.async), 32 x 16B per thread ----
    {
        #pragma unroll
        for (int s = 0; s < 32; s++) {
            const int seg = tid + s * 256;
            const int r   = seg >> 6;         // 0..127
            const int cg  = seg & 63;         // 16B group along K
            const int kc  = cg >> 3, b16 = cg & 7;
            const void* src = g_neb + (size_t)(iBase + r) * D + cg * 8;
            const uint32_t dst = Ab + kc * A_CH + r * 128 +
                                 ((uint32_t)(b16 ^ (r & 7)) << 4);
            asm volatile("cp.async.cg.shared.global [%0], [%1], 16;"
                         :: "r"(dst), "l"(src));
        }
        asm volatile("cp.async.commit_group;" ::: "memory");
    }

    // per-lane ldmatrix address components (row&7 == l&7 always: swizzle const)
    const uint32_t rowA = (uint32_t)(mw * 64 + (l & 15)) * 128;
    const uint32_t kbA  = (uint32_t)(l >> 4);           // 0/1
    const uint32_t rowB = (uint32_t)(nw * 64 + ((l >> 4) << 3) + (l & 7)) * 128;
    const uint32_t kbB  = (uint32_t)((l >> 3) & 1);
    const uint32_t xr   = (uint32_t)(l & 7);

    float rs[8];
    #pragma unroll
    for (int q = 0; q < 8; q++) rs[q] = 0.f;

    for (int iter = 0; iter < 16; iter++) {
        const int jb = jHalf + iter * 256;

        // prefetch chunk 0 -> Bb0
        #pragma unroll
        for (int s = 0; s < 8; s++) {
            const int seg = tid + s * 256;
            const int r = seg >> 3, b16 = seg & 7;
            const void* src = g_neb + (size_t)(jb + r) * D + b16 * 8;
            const uint32_t dst = Bb0 + r * 128 + ((uint32_t)(b16 ^ (r & 7)) << 4);
            asm volatile("cp.async.cg.shared.global [%0], [%1], 16;"
                         :: "r"(dst), "l"(src));
        }
        asm volatile("cp.async.commit_group;" ::: "memory");

        float c[4][8][4];
        #pragma unroll
        for (int mf = 0; mf < 4; mf++)
            #pragma unroll
            for (int nf = 0; nf < 8; nf++)
                #pragma unroll
                for (int q = 0; q < 4; q++) c[mf][nf][q] = 0.f;

        #pragma unroll 1
        for (int kc = 0; kc < 8; kc++) {
            asm volatile("cp.async.wait_group 0;" ::: "memory");
            __syncthreads();     // chunk kc visible; all warps past compute(kc-1)

            if (kc < 7) {        // prefetch kc+1 into the buffer kc-1 used
                const uint32_t bufN = ((kc + 1) & 1) ? Bb1 : Bb0;
                #pragma unroll
                for (int s = 0; s < 8; s++) {
                    const int seg = tid + s * 256;
                    const int r = seg >> 3, b16 = seg & 7;
                    const void* src = g_neb + (size_t)(jb + r) * D + (kc + 1) * 64 + b16 * 8;
                    const uint32_t dst = bufN + r * 128 + ((uint32_t)(b16 ^ (r & 7)) << 4);
                    asm volatile("cp.async.cg.shared.global [%0], [%1], 16;"
                                 :: "r"(dst), "l"(src));
                }
                asm volatile("cp.async.commit_group;" ::: "memory");
            }

            const uint32_t Bbuf  = (kc & 1) ? Bb1 : Bb0;
            const uint32_t Abase = Ab + kc * A_CH;

            #pragma unroll
            for (int ks = 0; ks < 4; ks++) {
                uint32_t b[8][2];
                #pragma unroll
                for (int nfp = 0; nfp < 4; nfp++) {
                    const uint32_t addr = Bbuf + rowB + nfp * 2048 +
                        ((((uint32_t)ks * 2 + kbB) ^ xr) << 4);
                    asm volatile(
                        "ldmatrix.sync.aligned.m8n8.x4.shared.b16 {%0,%1,%2,%3}, [%4];"
                        : "=r"(b[nfp*2][0]), "=r"(b[nfp*2][1]),
                          "=r"(b[nfp*2+1][0]), "=r"(b[nfp*2+1][1])
                        : "r"(addr));
                }
                #pragma unroll
                for (int mf = 0; mf < 4; mf++) {
                    uint32_t a0, a1, a2, a3;
                    const uint32_t addr = Abase + rowA + mf * 2048 +
                        ((((uint32_t)ks * 2 + kbA) ^ xr) << 4);
                    asm volatile(
                        "ldmatrix.sync.aligned.m8n8.x4.shared.b16 {%0,%1,%2,%3}, [%4];"
                        : "=r"(a0), "=r"(a1), "=r"(a2), "=r"(a3) : "r"(addr));
                    #pragma unroll
                    for (int nf = 0; nf < 8; nf++) {
                        asm volatile(
                            "mma.sync.aligned.m16n8k16.row.col.f32.bf16.bf16.f32 "
                            "{%0,%1,%2,%3}, {%4,%5,%6,%7}, {%8,%9}, {%0,%1,%2,%3};"
                            : "+f"(c[mf][nf][0]), "+f"(c[mf][nf][1]),
                              "+f"(c[mf][nf][2]), "+f"(c[mf][nf][3])
                            : "r"(a0), "r"(a1), "r"(a2), "r"(a3),
                              "r"(b[nf][0]), "r"(b[nf][1]));
                    }
                }
            }
        }

        // fold: rs += sum_cols exp(2*sim)
        #pragma unroll
        for (int mf = 0; mf < 4; mf++)
            #pragma unroll
            for (int nf = 0; nf < 8; nf++) {
                rs[mf*2]   += ex2f(c[mf][nf][0] * CEXP) + ex2f(c[mf][nf][1] * CEXP);
                rs[mf*2+1] += ex2f(c[mf][nf][2] * CEXP) + ex2f(c[mf][nf][3] * CEXP);
            }
    }

    // cross-lane: quad (same row, different cols)
    #pragma unroll
    for (int q = 0; q < 8; q++) {
        rs[q] += __shfl_xor_sync(0xffffffffu, rs[q], 1);
        rs[q] += __shfl_xor_sync(0xffffffffu, rs[q], 2);
    }

    __syncthreads();   // everyone done with B buffers
    float* red = reinterpret_cast<float*>(smem + 8 * A_CH);   // reuse Bb0
    if ((l & 3) == 0) {
        #pragma unroll
        for (int mf = 0; mf < 4; mf++) {
            const int r0 = mw * 64 + mf * 16 + (l >> 2);
            red[r0 * 4 + nw]       = rs[mf*2];
            red[(r0 + 8) * 4 + nw] = rs[mf*2+1];
        }
    }
    __syncthreads();
    if (tid < 128) {
        const float v = red[tid*4] + red[tid*4+1] + red[tid*4+2] + red[tid*4+3];
        g_rs[blockIdx.y * N + iBase + tid] = v;
    }
}

// ---------------------------------------------------------------------------
// K3: finalize  sum_i [ log(rs0_i + rs1_i) - 2*pos_i ] / (2N)
// ---------------------------------------------------------------------------
__global__ __launch_bounds__(256) void finalize_kernel(float* __restrict__ out) {
    const int tid = threadIdx.x;
    float s = 0.f;
    for (int i = tid; i < N; i += 256) {
        const float r = g_rs[i] + g_rs[N + i];
        s += __logf(r) - 2.0f * g_pos[i];
    }
    #pragma unroll
    for (int o = 16; o > 0; o >>= 1) s += __shfl_xor_sync(0xffffffffu, s, o);
    __shared__ float sh[8];
    const int w = tid >> 5, l = tid & 31;
    if (l == 0) sh[w] = s;
    __syncthreads();
    if (tid == 0) {
        float t = 0.f;
        #pragma unroll
        for (int i = 0; i < 8; i++) t += sh[i];
        out[0] = t / (2.0f * (float)N);
    }
}

// ---------------------------------------------------------------------------
extern "C" void kernel_launch(void* const* d_in, const int* in_sizes, int n_in,
                              void* d_out, int out_size) {
    const float* embeddings = (const float*)d_in[0];
    const float* targets    = (const float*)d_in[1];
    float* out = (float*)d_out;
    (void)in_sizes; (void)n_in; (void)out_size;

    cudaFuncSetAttribute(sim_kernel, cudaFuncAttributeMaxDynamicSharedMemorySize, SMEM_REQ);

    prep_kernel<<<N, 128>>>(embeddings, targets);
    sim_kernel<<<dim3(64, 2), 256, SMEM_REQ>>>();
    finalize_kernel<<<1, 256>>>(out);
}